// round 1
// baseline (speedup 1.0000x reference)
#include <cuda_runtime.h>
#include <math.h>

// Problem shape (fixed by the dataset)
#define BB 16
#define NN 8192
#define DD 128
#define HH 64
#define EE 64
#define EPS_LN 1e-5f

#define BLK1 64               // blocks per batch in pass 1
#define ROWS1 (NN / BLK1)     // 128 rows per pass-1 block
#define TILE 64               // rows per pass-3 tile
#define XP 132                // padded Xs row stride (floats)

// ---------------- scratch (__device__ globals; no allocation allowed) -------
__device__ float  d_partial[BB][BLK1][DD];  // per-block column sums of (x-mu)*rstd
__device__ float2 d_stats[BB * NN];         // per-row {mu, rstd}
__device__ float  d_G[BB][DD * EE];         // folded per-batch matrix ln_w[d]*M_b[d][e]
__device__ float  d_u[BB][EE];              // col sums of G
__device__ float  d_h[BB][EE];              // constant epilogue term

// ============================ Pass 1: row stats + column sums ===============
__global__ void k1_stats(const float* __restrict__ x) {
    int b    = blockIdx.y;
    int w    = threadIdx.x >> 5;
    int lane = threadIdx.x & 31;
    int rowbase = blockIdx.x * ROWS1 + w * (ROWS1 / 8);

    const float4* xb = (const float4*)(x + (size_t)b * NN * DD);

    float4 acc = make_float4(0.f, 0.f, 0.f, 0.f);
    #pragma unroll 4
    for (int rr = 0; rr < ROWS1 / 8; rr++) {
        int row = rowbase + rr;
        float4 v = xb[row * (DD / 4) + lane];
        float s = v.x + v.y + v.z + v.w;
        float q = v.x * v.x + v.y * v.y + v.z * v.z + v.w * v.w;
        #pragma unroll
        for (int o = 16; o > 0; o >>= 1) {
            s += __shfl_xor_sync(0xffffffffu, s, o);
            q += __shfl_xor_sync(0xffffffffu, q, o);
        }
        float mu   = s * (1.0f / DD);
        float var  = q * (1.0f / DD) - mu * mu;
        float rstd = rsqrtf(var + EPS_LN);
        if (lane == 0) d_stats[b * NN + row] = make_float2(mu, rstd);
        acc.x += (v.x - mu) * rstd;
        acc.y += (v.y - mu) * rstd;
        acc.z += (v.z - mu) * rstd;
        acc.w += (v.w - mu) * rstd;
    }

    __shared__ float sred[8][DD];
    ((float4*)sred[w])[lane] = acc;
    __syncthreads();
    if (threadIdx.x < DD) {
        float s = 0.f;
        #pragma unroll
        for (int ww = 0; ww < 8; ww++) s += sred[ww][threadIdx.x];
        d_partial[b][blockIdx.x][threadIdx.x] = s;
    }
}

// ============================ Pass 2: per-batch fold =========================
// One block per batch. Computes xbar -> lm -> M -> G, u, h. Deterministic.
#define SWRP 65   // padded stride for sWr / sM (bank-conflict-free)
#define K2_SMEM_FLOATS (DD * SWRP /*sWr*/ + HH * EE /*sP*/ + DD * SWRP /*sM*/ + DD + HH + EE)

__global__ void __launch_bounds__(256) k2_prep(
    const float* __restrict__ ln_w, const float* __restrict__ ln_b,
    const float* __restrict__ Wl,   const float* __restrict__ bl,
    const float* __restrict__ Wr,   const float* __restrict__ br,
    const float* __restrict__ Wo,   const float* __restrict__ bo) {
    extern __shared__ float sm[];
    float* sWr = sm;                    // [DD][SWRP]
    float* sP  = sWr + DD * SWRP;       // [HH][EE]  : lm[h]*Wo[h][e]
    float* sM  = sP + HH * EE;          // [DD][SWRP]
    float* sx  = sM + DD * SWRP;        // [DD]  xbar (post-affine)
    float* slm = sx + DD;               // [HH]
    float* sc  = slm + HH;              // [EE]

    int b = blockIdx.x, tid = threadIdx.x;

    // load Wr padded
    for (int i = tid; i < DD * HH; i += 256) {
        int d = i >> 6, h = i & 63;
        sWr[d * SWRP + h] = Wr[i];
    }
    // xbar[d] = ln_w[d] * mean_n((x-mu)*rstd) + ln_b[d]
    if (tid < DD) {
        float s = 0.f;
        for (int p = 0; p < BLK1; p++) s += d_partial[b][p][tid];
        sx[tid] = ln_w[tid] * (s * (1.0f / NN)) + ln_b[tid];
    }
    __syncthreads();
    // lm[h] = xbar @ Wl + bl
    if (tid < HH) {
        float a = bl[tid];
        for (int d = 0; d < DD; d++) a += sx[d] * Wl[d * HH + tid];
        slm[tid] = a;
    }
    __syncthreads();
    // P[h][e] = lm[h] * Wo[h][e]
    for (int i = tid; i < HH * EE; i += 256) sP[i] = slm[i / EE] * Wo[i];
    __syncthreads();
    // c[e] = sum_h br[h]*P[h][e] + bo[e]
    if (tid < EE) {
        float a = bo[tid];
        for (int h = 0; h < HH; h++) a += br[h] * sP[h * EE + tid];
        sc[tid] = a;
    }
    // M[d][e] = sum_h Wr[d][h] * P[h][e]   (thread: d = tid>>1, 32 e's)
    {
        int d = tid >> 1, e0 = (tid & 1) * 32;
        float acc[32];
        #pragma unroll
        for (int e = 0; e < 32; e++) acc[e] = 0.f;
        for (int h = 0; h < HH; h++) {
            float wr = sWr[d * SWRP + h];
            const float* p = &sP[h * EE + e0];
            #pragma unroll
            for (int e = 0; e < 32; e++) acc[e] += wr * p[e];
        }
        float* m = &sM[d * SWRP + e0];
        #pragma unroll
        for (int e = 0; e < 32; e++) m[e] = acc[e];
    }
    __syncthreads();
    // G[d][e] = ln_w[d]*M ; u[e] = col-sum of G ; h[e] = sum_d ln_b[d]*M + c[e]
    float* Gb = d_G[b];
    for (int i = tid; i < DD * EE; i += 256) {
        int d = i >> 6, e = i & 63;
        Gb[i] = ln_w[d] * sM[d * SWRP + e];
    }
    if (tid < EE) {
        float su = 0.f, shv = 0.f;
        for (int d = 0; d < DD; d++) {
            float m = sM[d * SWRP + tid];
            su  += ln_w[d] * m;
            shv += ln_b[d] * m;
        }
        d_u[b][tid] = su;
        d_h[b][tid] = shv + sc[tid];
    }
}

// ============================ Pass 3: fused main GEMM ========================
// out[b,n,e] = rstd_n*( (x_row @ G_b)[e] - mu_n*u[e] ) + h[e]
#define K3_SMEM_FLOATS (DD * EE /*Gs*/ + TILE * XP /*Xs*/ + EE /*su*/ + EE /*sh*/ + 2 * TILE /*stats*/)

__global__ void __launch_bounds__(256) k3_gemm(const float* __restrict__ x,
                                               float* __restrict__ out) {
    extern __shared__ float sm[];
    float*  Gs  = sm;                       // [DD][EE] row-major
    float*  Xs  = Gs + DD * EE;             // [TILE][XP] raw x
    float*  su  = Xs + TILE * XP;           // [EE]
    float*  sh  = su + EE;                  // [EE]
    float2* sst = (float2*)(sh + EE);       // [TILE] {mu, rstd}

    int b    = blockIdx.y;
    int tile = blockIdx.x;
    int tid  = threadIdx.x;
    int row0 = tile * TILE;

    // load G (coalesced float4)
    {
        const float4* g4  = (const float4*)d_G[b];
        float4*       Gs4 = (float4*)Gs;
        #pragma unroll
        for (int i = 0; i < (DD * EE / 4) / 256; i++)
            Gs4[tid + i * 256] = g4[tid + i * 256];
    }
    // load X tile (raw, no normalization needed)
    {
        const float4* xb = (const float4*)(x + ((size_t)b * NN + row0) * DD);
        #pragma unroll
        for (int i = 0; i < (TILE * DD / 4) / 256; i++) {
            int fid = tid + i * 256;
            int r = fid >> 5, kq = fid & 31;
            float4 v = xb[r * (DD / 4) + kq];
            *(float4*)&Xs[r * XP + 4 * kq] = v;
        }
    }
    if (tid < EE) { su[tid] = d_u[b][tid]; sh[tid] = d_h[b][tid]; }
    if (tid < TILE) sst[tid] = d_stats[b * NN + row0 + tid];
    __syncthreads();

    int ty = tid >> 4, tx = tid & 15;   // 16x16 threads, 4x4 outputs each
    unsigned long long acc[4][2];       // packed f32x2 accumulators (4 rows x 4 e)
    #pragma unroll
    for (int i = 0; i < 4; i++) { acc[i][0] = 0ull; acc[i][1] = 0ull; }

    const float* xrow[4];
    #pragma unroll
    for (int i = 0; i < 4; i++) xrow[i] = &Xs[(4 * ty + i) * XP];
    const float* gb = &Gs[4 * tx];

    for (int k = 0; k < DD; k += 4) {
        float a[4][4];
        #pragma unroll
        for (int i = 0; i < 4; i++) {
            float4 v = *(const float4*)(xrow[i] + k);
            a[i][0] = v.x; a[i][1] = v.y; a[i][2] = v.z; a[i][3] = v.w;
        }
        #pragma unroll
        for (int kk = 0; kk < 4; kk++) {
            ulonglong2 g = *(const ulonglong2*)(gb + (size_t)(k + kk) * EE);
            #pragma unroll
            for (int i = 0; i < 4; i++) {
                unsigned long long ap;
                asm("mov.b64 %0, {%1, %1};" : "=l"(ap) : "r"(__float_as_uint(a[i][kk])));
                asm("fma.rn.f32x2 %0, %1, %2, %0;" : "+l"(acc[i][0]) : "l"(ap), "l"(g.x));
                asm("fma.rn.f32x2 %0, %1, %2, %0;" : "+l"(acc[i][1]) : "l"(ap), "l"(g.y));
            }
        }
    }

    // epilogue: out = rstd*(acc - mu*u) + h
    #pragma unroll
    for (int i = 0; i < 4; i++) {
        int r = 4 * ty + i;
        float2 st = sst[r];
        float mu = st.x, rstd = st.y;
        unsigned lo0, hi0, lo1, hi1;
        asm("mov.b64 {%0,%1}, %2;" : "=r"(lo0), "=r"(hi0) : "l"(acc[i][0]));
        asm("mov.b64 {%0,%1}, %2;" : "=r"(lo1), "=r"(hi1) : "l"(acc[i][1]));
        int e0 = 4 * tx;
        float4 o;
        o.x = rstd * (__uint_as_float(lo0) - mu * su[e0 + 0]) + sh[e0 + 0];
        o.y = rstd * (__uint_as_float(hi0) - mu * su[e0 + 1]) + sh[e0 + 1];
        o.z = rstd * (__uint_as_float(lo1) - mu * su[e0 + 2]) + sh[e0 + 2];
        o.w = rstd * (__uint_as_float(hi1) - mu * su[e0 + 3]) + sh[e0 + 3];
        *(float4*)&out[(((size_t)b * NN + row0 + r) * EE) + e0] = o;
    }
}

// ============================ launch =========================================
extern "C" void kernel_launch(void* const* d_in, const int* in_sizes, int n_in,
                              void* d_out, int out_size) {
    const float* x    = (const float*)d_in[0];
    const float* ln_w = (const float*)d_in[1];
    const float* ln_b = (const float*)d_in[2];
    const float* Wl   = (const float*)d_in[3];
    const float* bl   = (const float*)d_in[4];
    const float* Wr   = (const float*)d_in[5];
    const float* br   = (const float*)d_in[6];
    const float* Wo   = (const float*)d_in[7];
    const float* bo   = (const float*)d_in[8];
    float* out = (float*)d_out;

    const int k2_smem = K2_SMEM_FLOATS * (int)sizeof(float);
    const int k3_smem = K3_SMEM_FLOATS * (int)sizeof(float);
    cudaFuncSetAttribute(k2_prep, cudaFuncAttributeMaxDynamicSharedMemorySize, k2_smem);
    cudaFuncSetAttribute(k3_gemm, cudaFuncAttributeMaxDynamicSharedMemorySize, k3_smem);

    k1_stats<<<dim3(BLK1, BB), 256>>>(x);
    k2_prep<<<BB, 256, k2_smem>>>(ln_w, ln_b, Wl, bl, Wr, br, Wo, bo);
    k3_gemm<<<dim3(NN / TILE, BB), 256, k3_smem>>>(x, out);
}